// round 1
// baseline (speedup 1.0000x reference)
#include <cuda_runtime.h>

// LorenzSDE ShARK integrator, strong order 1.5, additive noise.
//   B = 4194304 elements, 5 steps, state dim 3.
//   inputs : x [B,3] f32, dW [B,5,3] f32, dH [B,5,3] f32 (standard normals)
//   output : y_T [B,3] f32
//
// HBM-streaming bound (604 MB total). Key design point: avoid scalar
// stride-60B global loads (L1tex wavefront explosion); instead stage
// through shared memory with fully coalesced float4 global traffic.
// LDS strides 15 and 3 are coprime to 32 -> conflict-free smem reads.

#ifndef BLOCK
#define BLOCK 256
#endif

__global__ __launch_bounds__(BLOCK) void lorenz_shark_kernel(
    const float* __restrict__ g_x,
    const float* __restrict__ g_dW,
    const float* __restrict__ g_dH,
    float* __restrict__ g_out)
{
    __shared__ float s_x[BLOCK * 3];    //  3 KB
    __shared__ float s_w[BLOCK * 15];   // 15 KB
    __shared__ float s_h[BLOCK * 15];   // 15 KB

    const int tid = threadIdx.x;
    const long long base = (long long)blockIdx.x * BLOCK;   // element index base

    // ---- stage: perfectly coalesced float4 loads ----
    // base*3 and base*15 are multiples of 4 (BLOCK=256), so float4 views are aligned.
    const float4* gx4 = reinterpret_cast<const float4*>(g_x  + base * 3);
    const float4* gw4 = reinterpret_cast<const float4*>(g_dW + base * 15);
    const float4* gh4 = reinterpret_cast<const float4*>(g_dH + base * 15);
    float4* sx4 = reinterpret_cast<float4*>(s_x);
    float4* sw4 = reinterpret_cast<float4*>(s_w);
    float4* sh4 = reinterpret_cast<float4*>(s_h);

    #pragma unroll
    for (int i = tid; i < (BLOCK * 3) / 4; i += BLOCK)
        sx4[i] = gx4[i];
    #pragma unroll
    for (int i = tid; i < (BLOCK * 15) / 4; i += BLOCK) {
        sw4[i] = gw4[i];
        sh4[i] = gh4[i];
    }
    __syncthreads();

    // ---- integrate: one element per thread, 5 steps fully unrolled ----
    const float DT   = 0.01f;
    const float CW   = 0.2f;                    // NOISE * sqrt(DT)        = 2*0.1
    const float CH   = 0.05773502691896258f;    // NOISE * sqrt(DT/12)
    const float SIG  = 10.0f;
    const float RHO  = 28.0f;
    const float BET  = 8.0f / 3.0f;
    const float A56  = (5.0f / 6.0f) * DT;      // 5/6 * h
    const float B56  = 5.0f / 6.0f;

    float y0 = s_x[tid * 3 + 0];
    float y1 = s_x[tid * 3 + 1];
    float y2 = s_x[tid * 3 + 2];

    #pragma unroll
    for (int s = 0; s < 5; ++s) {
        const float w0 = s_w[tid * 15 + s * 3 + 0] * CW;
        const float w1 = s_w[tid * 15 + s * 3 + 1] * CW;
        const float w2 = s_w[tid * 15 + s * 3 + 2] * CW;
        const float h0 = s_h[tid * 15 + s * 3 + 0] * CH;
        const float h1 = s_h[tid * 15 + s * 3 + 1] * CH;
        const float h2 = s_h[tid * 15 + s * 3 + 2] * CH;

        // z1 = y + gH
        const float z10 = y0 + h0;
        const float z11 = y1 + h1;
        const float z12 = y2 + h2;
        // f1 = drift(z1)
        const float f10 = SIG * (z11 - z10);
        const float f11 = z10 * (RHO - z12) - z11;
        const float f12 = z10 * z11 - BET * z12;
        // z2 = y + (5/6) h f1 + (5/6) gW + gH
        const float z20 = y0 + A56 * f10 + B56 * w0 + h0;
        const float z21 = y1 + A56 * f11 + B56 * w1 + h1;
        const float z22 = y2 + A56 * f12 + B56 * w2 + h2;
        // f2 = drift(z2)
        const float f20 = SIG * (z21 - z20);
        const float f21 = z20 * (RHO - z22) - z21;
        const float f22 = z20 * z21 - BET * z22;
        // y1 = y + h (0.4 f1 + 0.6 f2) + gW
        y0 = y0 + DT * (0.4f * f10 + 0.6f * f20) + w0;
        y1 = y1 + DT * (0.4f * f11 + 0.6f * f21) + w1;
        y2 = y2 + DT * (0.4f * f12 + 0.6f * f22) + w2;
    }

    // ---- write back through smem for coalesced float4 stores ----
    // Each thread writes only its own 3 slots (disjoint); barrier below
    // orders these writes before the cross-thread float4 store loop.
    s_x[tid * 3 + 0] = y0;
    s_x[tid * 3 + 1] = y1;
    s_x[tid * 3 + 2] = y2;
    __syncthreads();

    float4* go4 = reinterpret_cast<float4*>(g_out + base * 3);
    #pragma unroll
    for (int i = tid; i < (BLOCK * 3) / 4; i += BLOCK)
        go4[i] = sx4[i];
}

extern "C" void kernel_launch(void* const* d_in, const int* in_sizes, int n_in,
                              void* d_out, int out_size) {
    const float* x  = (const float*)d_in[0];
    const float* dW = (const float*)d_in[1];
    const float* dH = (const float*)d_in[2];
    float* out = (float*)d_out;

    const int n = in_sizes[0] / 3;          // batch size (4194304; multiple of 256)
    const int grid = n / BLOCK;
    lorenz_shark_kernel<<<grid, BLOCK>>>(x, dW, dH, out);
}

// round 2
// speedup vs baseline: 1.1479x; 1.1479x over previous
#include <cuda_runtime.h>
#include <cstdint>

// LorenzSDE ShARK integrator — persistent double-buffered cp.async pipeline.
//   B = 4194304 elements, 5 steps, dim 3. 604 MB total traffic -> HBM bound.
//
// R1 showed DRAM=70.7% with a bursty load->sync->compute block structure.
// This version keeps the DRAM stream continuous: each block grid-strides over
// 128-element tiles; tile i+1 streams into smem buffer b^1 via cp.async.cg
// (L1-bypass) while tile i is computed out of buffer b.

#define BLOCK 128
#define TILE  128
#define W4    (TILE * 15 / 4)   // 480 float4 per tile for dW (and dH)
#define X4    (TILE * 3 / 4)    // 96 float4 per tile for x / out

__device__ __forceinline__ void cp16(void* sptr, const void* gptr) {
    uint32_t s = (uint32_t)__cvta_generic_to_shared(sptr);
    asm volatile("cp.async.cg.shared.global [%0], [%1], 16;"
                 :: "r"(s), "l"(gptr) : "memory");
}
#define CP_COMMIT() asm volatile("cp.async.commit_group;" ::: "memory")
#define CP_WAIT(N)  asm volatile("cp.async.wait_group %0;" :: "n"(N) : "memory")

__global__ __launch_bounds__(BLOCK) void lorenz_shark_kernel(
    const float* __restrict__ g_x,
    const float* __restrict__ g_dW,
    const float* __restrict__ g_dH,
    float* __restrict__ g_out,
    int n_tiles)
{
    __shared__ float4 s_w[2][W4];   // 2 x 7.5 KB
    __shared__ float4 s_h[2][W4];   // 2 x 7.5 KB
    __shared__ float4 s_x[2][X4];   // 2 x 1.5 KB
    __shared__ float4 s_o[X4];      // 1.5 KB     (34.5 KB total -> 6 CTAs/SM)

    const int tid = threadIdx.x;

    const float DT  = 0.01f;
    const float CW  = 0.2f;                  // NOISE*sqrt(DT)
    const float CH  = 0.05773502691896258f;  // NOISE*sqrt(DT/12)
    const float SIG = 10.0f;
    const float RHO = 28.0f;
    const float BET = 8.0f / 3.0f;
    const float A56 = (5.0f / 6.0f) * DT;
    const float B56 = 5.0f / 6.0f;

    int tile = blockIdx.x;
    if (tile >= n_tiles) return;

    // ---- prefetch helper (issues this thread's share of one tile) ----
    auto prefetch = [&](int buf, int t) {
        const float4* gw = reinterpret_cast<const float4*>(g_dW + (long long)t * TILE * 15);
        const float4* gh = reinterpret_cast<const float4*>(g_dH + (long long)t * TILE * 15);
        const float4* gx = reinterpret_cast<const float4*>(g_x  + (long long)t * TILE * 3);
        #pragma unroll
        for (int i = tid; i < W4; i += BLOCK) {
            cp16(&s_w[buf][i], gw + i);
            cp16(&s_h[buf][i], gh + i);
        }
        if (tid < X4) cp16(&s_x[buf][tid], gx + tid);
    };

    prefetch(0, tile);
    CP_COMMIT();

    int buf = 0;
    for (; tile < n_tiles; tile += gridDim.x) {
        const int next = tile + gridDim.x;
        if (next < n_tiles) {
            prefetch(buf ^ 1, next);
            CP_COMMIT();
            CP_WAIT(1);          // current tile's group complete
        } else {
            CP_WAIT(0);
        }
        __syncthreads();         // all threads' cp.async data visible

        const float* w = reinterpret_cast<const float*>(s_w[buf]);
        const float* h = reinterpret_cast<const float*>(s_h[buf]);
        const float* x = reinterpret_cast<const float*>(s_x[buf]);

        float y0 = x[tid * 3 + 0];
        float y1 = x[tid * 3 + 1];
        float y2 = x[tid * 3 + 2];

        #pragma unroll
        for (int s = 0; s < 5; ++s) {
            const float w0 = w[tid * 15 + s * 3 + 0] * CW;
            const float w1 = w[tid * 15 + s * 3 + 1] * CW;
            const float w2 = w[tid * 15 + s * 3 + 2] * CW;
            const float h0 = h[tid * 15 + s * 3 + 0] * CH;
            const float h1 = h[tid * 15 + s * 3 + 1] * CH;
            const float h2 = h[tid * 15 + s * 3 + 2] * CH;

            const float z10 = y0 + h0;
            const float z11 = y1 + h1;
            const float z12 = y2 + h2;
            const float f10 = SIG * (z11 - z10);
            const float f11 = z10 * (RHO - z12) - z11;
            const float f12 = z10 * z11 - BET * z12;
            const float z20 = y0 + A56 * f10 + B56 * w0 + h0;
            const float z21 = y1 + A56 * f11 + B56 * w1 + h1;
            const float z22 = y2 + A56 * f12 + B56 * w2 + h2;
            const float f20 = SIG * (z21 - z20);
            const float f21 = z20 * (RHO - z22) - z21;
            const float f22 = z20 * z21 - BET * z22;
            y0 = y0 + DT * (0.4f * f10 + 0.6f * f20) + w0;
            y1 = y1 + DT * (0.4f * f11 + 0.6f * f21) + w1;
            y2 = y2 + DT * (0.4f * f12 + 0.6f * f22) + w2;
        }

        float* so = reinterpret_cast<float*>(s_o);
        so[tid * 3 + 0] = y0;
        so[tid * 3 + 1] = y1;
        so[tid * 3 + 2] = y2;
        __syncthreads();         // order s_o writes before cross-thread reads

        float4* go = reinterpret_cast<float4*>(g_out + (long long)tile * TILE * 3);
        if (tid < X4) go[tid] = s_o[tid];
        // Next iteration's first __syncthreads separates these s_o reads
        // from the next tile's s_o writes.

        buf ^= 1;
    }
}

extern "C" void kernel_launch(void* const* d_in, const int* in_sizes, int n_in,
                              void* d_out, int out_size) {
    const float* x  = (const float*)d_in[0];
    const float* dW = (const float*)d_in[1];
    const float* dH = (const float*)d_in[2];
    float* out = (float*)d_out;

    const int n = in_sizes[0] / 3;        // 4194304, multiple of TILE
    const int n_tiles = n / TILE;         // 32768
    int grid = 152 * 6;                   // 6 CTAs/SM persistent
    if (grid > n_tiles) grid = n_tiles;
    lorenz_shark_kernel<<<grid, BLOCK>>>(x, dW, dH, out, n_tiles);
}

// round 3
// speedup vs baseline: 1.1785x; 1.0266x over previous
#include <cuda_runtime.h>
#include <cstdint>

// LorenzSDE ShARK — persistent double-buffered cp.async pipeline, v3.
//   Changes vs R2 (95.0us, DRAM 81.8%):
//   - x loaded directly into registers (prefetched one tile ahead), output
//     stored directly from registers -> smem 34.5KB -> 30KB -> 7 CTAs/SM.
//   - one __syncthreads per tile instead of two.
//   Only the big dW/dH streams (11/12 of read traffic) stay smem-staged.

#define BLOCK 128
#define TILE  128
#define W4    (TILE * 15 / 4)   // 480 float4 per tile for dW (and dH)

__device__ __forceinline__ void cp16(void* sptr, const void* gptr) {
    uint32_t s = (uint32_t)__cvta_generic_to_shared(sptr);
    asm volatile("cp.async.cg.shared.global [%0], [%1], 16;"
                 :: "r"(s), "l"(gptr) : "memory");
}
#define CP_COMMIT() asm volatile("cp.async.commit_group;" ::: "memory")
#define CP_WAIT(N)  asm volatile("cp.async.wait_group %0;" :: "n"(N) : "memory")

__global__ __launch_bounds__(BLOCK) void lorenz_shark_kernel(
    const float* __restrict__ g_x,
    const float* __restrict__ g_dW,
    const float* __restrict__ g_dH,
    float* __restrict__ g_out,
    int n_tiles)
{
    __shared__ float4 s_w[2][W4];   // 2 x 7.5 KB
    __shared__ float4 s_h[2][W4];   // 2 x 7.5 KB -> 30 KB total, 7 CTAs/SM

    const int tid = threadIdx.x;

    const float DT  = 0.01f;
    const float CW  = 0.2f;                  // NOISE*sqrt(DT)
    const float CH  = 0.05773502691896258f;  // NOISE*sqrt(DT/12)
    const float SIG = 10.0f;
    const float RHO = 28.0f;
    const float BET = 8.0f / 3.0f;
    const float A56 = (5.0f / 6.0f) * DT;
    const float B56 = 5.0f / 6.0f;

    int tile = blockIdx.x;
    if (tile >= n_tiles) return;

    auto prefetch_wh = [&](int buf, int t) {
        const float4* gw = reinterpret_cast<const float4*>(g_dW + (long long)t * TILE * 15);
        const float4* gh = reinterpret_cast<const float4*>(g_dH + (long long)t * TILE * 15);
        #pragma unroll
        for (int i = tid; i < W4; i += BLOCK) {
            cp16(&s_w[buf][i], gw + i);
            cp16(&s_h[buf][i], gh + i);
        }
    };

    // ---- prologue: prefetch tile 0 (smem) + x(tile 0) (regs) ----
    prefetch_wh(0, tile);
    CP_COMMIT();
    const float* xp = g_x + (long long)tile * TILE * 3 + tid * 3;
    float xr0 = xp[0], xr1 = xp[1], xr2 = xp[2];

    int buf = 0;
    for (; tile < n_tiles; tile += gridDim.x) {
        const int next = tile + gridDim.x;

        // issue next tile's async loads, then prefetch next x into regs
        float nx0 = 0.f, nx1 = 0.f, nx2 = 0.f;
        if (next < n_tiles) {
            prefetch_wh(buf ^ 1, next);
            CP_COMMIT();
            const float* nxp = g_x + (long long)next * TILE * 3 + tid * 3;
            nx0 = nxp[0]; nx1 = nxp[1]; nx2 = nxp[2];
            CP_WAIT(1);          // current tile's group complete
        } else {
            CP_WAIT(0);
        }
        __syncthreads();         // all threads' cp.async data visible

        const float* w = reinterpret_cast<const float*>(s_w[buf]);
        const float* h = reinterpret_cast<const float*>(s_h[buf]);

        float y0 = xr0, y1 = xr1, y2 = xr2;

        #pragma unroll
        for (int s = 0; s < 5; ++s) {
            const float w0 = w[tid * 15 + s * 3 + 0] * CW;
            const float w1 = w[tid * 15 + s * 3 + 1] * CW;
            const float w2 = w[tid * 15 + s * 3 + 2] * CW;
            const float h0 = h[tid * 15 + s * 3 + 0] * CH;
            const float h1 = h[tid * 15 + s * 3 + 1] * CH;
            const float h2 = h[tid * 15 + s * 3 + 2] * CH;

            const float z10 = y0 + h0;
            const float z11 = y1 + h1;
            const float z12 = y2 + h2;
            const float f10 = SIG * (z11 - z10);
            const float f11 = z10 * (RHO - z12) - z11;
            const float f12 = z10 * z11 - BET * z12;
            const float z20 = y0 + A56 * f10 + B56 * w0 + h0;
            const float z21 = y1 + A56 * f11 + B56 * w1 + h1;
            const float z22 = y2 + A56 * f12 + B56 * w2 + h2;
            const float f20 = SIG * (z21 - z20);
            const float f21 = z20 * (RHO - z22) - z21;
            const float f22 = z20 * z21 - BET * z22;
            y0 = y0 + DT * (0.4f * f10 + 0.6f * f20) + w0;
            y1 = y1 + DT * (0.4f * f11 + 0.6f * f21) + w1;
            y2 = y2 + DT * (0.4f * f12 + 0.6f * f22) + w2;
        }

        // direct store (stride-3 scalar; sectors fully written, traffic unchanged)
        float* op = g_out + (long long)tile * TILE * 3 + tid * 3;
        op[0] = y0; op[1] = y1; op[2] = y2;

        // barrier before next tile's smem reads also separates this tile's
        // smem reads from the *following* prefetch overwrite of buf.
        __syncthreads();

        xr0 = nx0; xr1 = nx1; xr2 = nx2;
        buf ^= 1;
    }
}

extern "C" void kernel_launch(void* const* d_in, const int* in_sizes, int n_in,
                              void* d_out, int out_size) {
    const float* x  = (const float*)d_in[0];
    const float* dW = (const float*)d_in[1];
    const float* dH = (const float*)d_in[2];
    float* out = (float*)d_out;

    const int n = in_sizes[0] / 3;        // 4194304, multiple of TILE
    const int n_tiles = n / TILE;         // 32768
    int grid = 152 * 7;                   // 7 CTAs/SM persistent (30KB smem each)
    if (grid > n_tiles) grid = n_tiles;
    lorenz_shark_kernel<<<grid, BLOCK>>>(x, dW, dH, out, n_tiles);
}

// round 4
// speedup vs baseline: 1.1967x; 1.0155x over previous
#include <cuda_runtime.h>
#include <cstdint>

// LorenzSDE ShARK — persistent double-buffered cp.async pipeline, v4.
//   Changes vs R3 (92.5us, DRAM 83.2%):
//   - grid = 1024: 32768 tiles / 1024 CTAs = exactly 32 tiles each (no ragged
//     tail; R3's 1064-CTA grid ran its last pass with only 80% of CTAs).
//   - streaming hints (.cs) on the scalar x loads and output stores
//     (use-once streams; keep them from displacing L2 lines of the
//     cp.async dW/dH stream).

#define BLOCK 128
#define TILE  128
#define W4    (TILE * 15 / 4)   // 480 float4 per tile for dW (and dH)
#define GRID  1024              // 32768 / 1024 = 32 tiles per CTA, exact

__device__ __forceinline__ void cp16(void* sptr, const void* gptr) {
    uint32_t s = (uint32_t)__cvta_generic_to_shared(sptr);
    asm volatile("cp.async.cg.shared.global [%0], [%1], 16;"
                 :: "r"(s), "l"(gptr) : "memory");
}
#define CP_COMMIT() asm volatile("cp.async.commit_group;" ::: "memory")
#define CP_WAIT(N)  asm volatile("cp.async.wait_group %0;" :: "n"(N) : "memory")

__global__ __launch_bounds__(BLOCK) void lorenz_shark_kernel(
    const float* __restrict__ g_x,
    const float* __restrict__ g_dW,
    const float* __restrict__ g_dH,
    float* __restrict__ g_out,
    int n_tiles)
{
    __shared__ float4 s_w[2][W4];   // 2 x 7.5 KB
    __shared__ float4 s_h[2][W4];   // 2 x 7.5 KB -> 30 KB total, 7 CTAs/SM

    const int tid = threadIdx.x;

    const float DT  = 0.01f;
    const float CW  = 0.2f;                  // NOISE*sqrt(DT)
    const float CH  = 0.05773502691896258f;  // NOISE*sqrt(DT/12)
    const float SIG = 10.0f;
    const float RHO = 28.0f;
    const float BET = 8.0f / 3.0f;
    const float A56 = (5.0f / 6.0f) * DT;
    const float B56 = 5.0f / 6.0f;

    int tile = blockIdx.x;
    if (tile >= n_tiles) return;

    auto prefetch_wh = [&](int buf, int t) {
        const float4* gw = reinterpret_cast<const float4*>(g_dW + (long long)t * TILE * 15);
        const float4* gh = reinterpret_cast<const float4*>(g_dH + (long long)t * TILE * 15);
        #pragma unroll
        for (int i = tid; i < W4; i += BLOCK) {
            cp16(&s_w[buf][i], gw + i);
            cp16(&s_h[buf][i], gh + i);
        }
    };

    // ---- prologue: prefetch tile 0 (smem) + x(tile 0) (regs, streaming) ----
    prefetch_wh(0, tile);
    CP_COMMIT();
    const float* xp = g_x + (long long)tile * TILE * 3 + tid * 3;
    float xr0 = __ldcs(xp + 0), xr1 = __ldcs(xp + 1), xr2 = __ldcs(xp + 2);

    int buf = 0;
    for (; tile < n_tiles; tile += GRID) {
        const int next = tile + GRID;

        float nx0 = 0.f, nx1 = 0.f, nx2 = 0.f;
        if (next < n_tiles) {
            prefetch_wh(buf ^ 1, next);
            CP_COMMIT();
            const float* nxp = g_x + (long long)next * TILE * 3 + tid * 3;
            nx0 = __ldcs(nxp + 0); nx1 = __ldcs(nxp + 1); nx2 = __ldcs(nxp + 2);
            CP_WAIT(1);          // current tile's group complete
        } else {
            CP_WAIT(0);
        }
        __syncthreads();         // all threads' cp.async data visible

        const float* w = reinterpret_cast<const float*>(s_w[buf]);
        const float* h = reinterpret_cast<const float*>(s_h[buf]);

        float y0 = xr0, y1 = xr1, y2 = xr2;

        #pragma unroll
        for (int s = 0; s < 5; ++s) {
            const float w0 = w[tid * 15 + s * 3 + 0] * CW;
            const float w1 = w[tid * 15 + s * 3 + 1] * CW;
            const float w2 = w[tid * 15 + s * 3 + 2] * CW;
            const float h0 = h[tid * 15 + s * 3 + 0] * CH;
            const float h1 = h[tid * 15 + s * 3 + 1] * CH;
            const float h2 = h[tid * 15 + s * 3 + 2] * CH;

            const float z10 = y0 + h0;
            const float z11 = y1 + h1;
            const float z12 = y2 + h2;
            const float f10 = SIG * (z11 - z10);
            const float f11 = z10 * (RHO - z12) - z11;
            const float f12 = z10 * z11 - BET * z12;
            const float z20 = y0 + A56 * f10 + B56 * w0 + h0;
            const float z21 = y1 + A56 * f11 + B56 * w1 + h1;
            const float z22 = y2 + A56 * f12 + B56 * w2 + h2;
            const float f20 = SIG * (z21 - z20);
            const float f21 = z20 * (RHO - z22) - z21;
            const float f22 = z20 * z21 - BET * z22;
            y0 = y0 + DT * (0.4f * f10 + 0.6f * f20) + w0;
            y1 = y1 + DT * (0.4f * f11 + 0.6f * f21) + w1;
            y2 = y2 + DT * (0.4f * f12 + 0.6f * f22) + w2;
        }

        // direct streaming store (stride-3 scalar; warp covers contiguous
        // 384B so sectors are fully written -> no write-allocate reads)
        float* op = g_out + (long long)tile * TILE * 3 + tid * 3;
        __stcs(op + 0, y0);
        __stcs(op + 1, y1);
        __stcs(op + 2, y2);

        // separates this tile's smem reads from the next prefetch that
        // overwrites this buffer.
        __syncthreads();

        xr0 = nx0; xr1 = nx1; xr2 = nx2;
        buf ^= 1;
    }
}

extern "C" void kernel_launch(void* const* d_in, const int* in_sizes, int n_in,
                              void* d_out, int out_size) {
    const float* x  = (const float*)d_in[0];
    const float* dW = (const float*)d_in[1];
    const float* dH = (const float*)d_in[2];
    float* out = (float*)d_out;

    const int n = in_sizes[0] / 3;        // 4194304, multiple of TILE
    const int n_tiles = n / TILE;         // 32768
    int grid = GRID;                      // exact 32 tiles/CTA, single wave
    if (grid > n_tiles) grid = n_tiles;
    lorenz_shark_kernel<<<grid, BLOCK>>>(x, dW, dH, out, n_tiles);
}